// round 1
// baseline (speedup 1.0000x reference)
#include <cuda_runtime.h>
#include <math.h>

#define TILE   16
#define HALO   18   // TILE + 2
#define CHN    12
#define HIDDEN 128
#define PERC   36
#define OUTC   9    // CHN - GENE_SIZE
#define HW     256
#define PIX    (HW*HW)

__global__ void __launch_bounds__(256)
isoca_fused_kernel(const float* __restrict__ x,
                   const float* __restrict__ rnd,
                   const float* __restrict__ w1w,
                   const float* __restrict__ w1b,
                   const float* __restrict__ w2w,
                   float* __restrict__ out)
{
    __shared__ float s_x[CHN][HALO][HALO];        // 15552 B
    __shared__ float s_w1[HIDDEN * PERC];         // 18432 B  [h][k] row-major
    __shared__ float s_w2[OUTC * HIDDEN];         //  4608 B  [o][h] row-major
    __shared__ float s_b[HIDDEN];                 //   512 B

    const int b   = blockIdx.z;
    const int ty0 = blockIdx.y * TILE;
    const int tx0 = blockIdx.x * TILE;
    const int tid = threadIdx.x;

    // ---- stage weights into SMEM ----
    for (int i = tid; i < HIDDEN * PERC; i += 256) s_w1[i] = w1w[i];
    for (int i = tid; i < OUTC * HIDDEN; i += 256) s_w2[i] = w2w[i];
    if (tid < HIDDEN) s_b[tid] = w1b[tid];

    // ---- stage x tile (+1 halo, circular wrap) ----
    const float* xb = x + (size_t)b * CHN * PIX;
    for (int i = tid; i < CHN * HALO * HALO; i += 256) {
        int c  = i / (HALO * HALO);
        int r  = i % (HALO * HALO);
        int yy = r / HALO;
        int xx = r % HALO;
        int gyw = (ty0 + yy - 1) & (HW - 1);
        int gxw = (tx0 + xx - 1) & (HW - 1);
        s_x[c][yy][xx] = xb[(size_t)c * PIX + gyw * HW + gxw];
    }
    __syncthreads();

    const int tx = tid & (TILE - 1);
    const int ty = tid >> 4;
    const int gy = ty0 + ty;
    const int gx = tx0 + tx;

    // ---- perception: perc = [x0,lap0, x1,lap1, ..., gn0..gn11] ----
    float perc[PERC];
    #pragma unroll
    for (int c = 0; c < CHN; c++) {
        float n00 = s_x[c][ty  ][tx  ], n01 = s_x[c][ty  ][tx+1], n02 = s_x[c][ty  ][tx+2];
        float n10 = s_x[c][ty+1][tx  ], n11 = s_x[c][ty+1][tx+1], n12 = s_x[c][ty+1][tx+2];
        float n20 = s_x[c][ty+2][tx  ], n21 = s_x[c][ty+2][tx+1], n22 = s_x[c][ty+2][tx+2];
        float lap = (n00 + n02 + n20 + n22) + 2.0f * (n01 + n10 + n12 + n21) - 12.0f * n11;
        float gxv = (n02 - n00) + 2.0f * (n12 - n10) + (n22 - n20);
        float gyv = (n20 - n00) + 2.0f * (n21 - n01) + (n22 - n02);
        perc[2*c]     = n11;
        perc[2*c + 1] = lap;
        perc[24 + c]  = sqrtf(gxv * gxv + gyv * gyv + 1e-8f);
    }

    // ---- life gate: 3x3 max-pool of channel 3, NON-circular (-inf padding) ----
    float mx = -INFINITY;
    #pragma unroll
    for (int dy = -1; dy <= 1; dy++) {
        #pragma unroll
        for (int dx = -1; dx <= 1; dx++) {
            int Y = gy + dy, X = gx + dx;
            if (Y >= 0 && Y < HW && X >= 0 && X < HW)
                mx = fmaxf(mx, s_x[3][ty + 1 + dy][tx + 1 + dx]);
        }
    }
    float life = (mx > 0.1f) ? 1.0f : 0.0f;
    float mask = floorf(rnd[(size_t)b * PIX + gy * HW + gx] + 0.5f);
    float gate = life * mask;

    // ---- MLP: 36 -> 128 (leaky 0.01) -> 9 ----
    float o[OUTC];
    #pragma unroll
    for (int i = 0; i < OUTC; i++) o[i] = 0.0f;

    #pragma unroll 4
    for (int h = 0; h < HIDDEN; h++) {
        float acc = s_b[h];
        const float* wr = &s_w1[h * PERC];
        #pragma unroll
        for (int k = 0; k < PERC; k++) acc = fmaf(wr[k], perc[k], acc);
        acc = (acc > 0.0f) ? acc : 0.01f * acc;
        #pragma unroll
        for (int oo = 0; oo < OUTC; oo++) o[oo] = fmaf(s_w2[oo * HIDDEN + h], acc, o[oo]);
    }

    // ---- write output: updated channels 0..8, gene channels 9..11 copied ----
    float* ob = out + (size_t)b * CHN * PIX;
    const size_t pix = (size_t)gy * HW + gx;
    #pragma unroll
    for (int c = 0; c < OUTC; c++)
        ob[(size_t)c * PIX + pix] = s_x[c][ty + 1][tx + 1] + o[c] * gate;
    #pragma unroll
    for (int c = OUTC; c < CHN; c++)
        ob[(size_t)c * PIX + pix] = s_x[c][ty + 1][tx + 1];
}

extern "C" void kernel_launch(void* const* d_in, const int* in_sizes, int n_in,
                              void* d_out, int out_size) {
    const float* x   = (const float*)d_in[0];
    const float* rnd = (const float*)d_in[1];
    const float* w1w = (const float*)d_in[2];
    const float* w1b = (const float*)d_in[3];
    const float* w2w = (const float*)d_in[4];
    float* out = (float*)d_out;

    dim3 grid(HW / TILE, HW / TILE, 16);   // (16, 16, 16) = 4096 blocks
    isoca_fused_kernel<<<grid, 256>>>(x, rnd, w1w, w1b, w2w, out);
}

// round 3
// speedup vs baseline: 1.5148x; 1.5148x over previous
#include <cuda_runtime.h>
#include <math.h>

#define TILE   16
#define HALO   18   // TILE + 2
#define CHN    12
#define HIDDEN 128
#define PERC   36
#define OUTC   9    // CHN - GENE_SIZE
#define HW     256
#define PIX    (HW*HW)

__device__ __forceinline__ void compute_perc(const float (*sx)[HALO][HALO],
                                             int ty, int tx, float* perc)
{
    #pragma unroll
    for (int c = 0; c < CHN; c++) {
        float n00 = sx[c][ty  ][tx  ], n01 = sx[c][ty  ][tx+1], n02 = sx[c][ty  ][tx+2];
        float n10 = sx[c][ty+1][tx  ], n11 = sx[c][ty+1][tx+1], n12 = sx[c][ty+1][tx+2];
        float n20 = sx[c][ty+2][tx  ], n21 = sx[c][ty+2][tx+1], n22 = sx[c][ty+2][tx+2];
        float lap = (n00 + n02 + n20 + n22) + 2.0f * (n01 + n10 + n12 + n21) - 12.0f * n11;
        float gxv = (n02 - n00) + 2.0f * (n12 - n10) + (n22 - n20);
        float gyv = (n20 - n00) + 2.0f * (n21 - n01) + (n22 - n02);
        perc[2*c]     = n11;
        perc[2*c + 1] = lap;
        perc[24 + c]  = sqrtf(gxv * gxv + gyv * gyv + 1e-8f);
    }
}

__global__ void __launch_bounds__(256)
isoca_fused_kernel(const float* __restrict__ x,
                   const float* __restrict__ rnd,
                   const float* __restrict__ w1w,
                   const float* __restrict__ w1b,
                   const float* __restrict__ w2w,
                   float* __restrict__ out)
{
    __shared__ float s_x[CHN][HALO][HALO];   // 15552 B
    __shared__ float s_w1[HIDDEN * PERC];    // 18432 B  [h][k], 144B rows (16B aligned)
    __shared__ float s_w2t[HIDDEN * 12];     //  6144 B  [h][o] padded to 12
    __shared__ float s_b[HIDDEN];            //   512 B
    __shared__ unsigned short s_list[256];   //   512 B
    __shared__ int s_cnt;                    // total ~41.2 KB

    const int b   = blockIdx.z;
    const int ty0 = blockIdx.y * TILE;
    const int tx0 = blockIdx.x * TILE;
    const int tid = threadIdx.x;

    if (tid == 0) s_cnt = 0;

    // ---- stage weights ----
    for (int i = tid; i < HIDDEN * PERC; i += 256) s_w1[i] = w1w[i];
    for (int i = tid; i < HIDDEN * 12; i += 256) {
        int h = i / 12, o = i % 12;
        s_w2t[i] = (o < OUTC) ? w2w[o * HIDDEN + h] : 0.0f;
    }
    if (tid < HIDDEN) s_b[tid] = w1b[tid];

    // ---- stage x tile (+1 halo, circular wrap) ----
    const float* xb = x + (size_t)b * CHN * PIX;
    for (int i = tid; i < CHN * HALO * HALO; i += 256) {
        int c  = i / (HALO * HALO);
        int r  = i % (HALO * HALO);
        int yy = r / HALO;
        int xx = r % HALO;
        int gyw = (ty0 + yy - 1) & (HW - 1);
        int gxw = (tx0 + xx - 1) & (HW - 1);
        s_x[c][yy][xx] = xb[(size_t)c * PIX + gyw * HW + gxw];
    }
    __syncthreads();

    // =========================== Phase A ===========================
    const int tx = tid & (TILE - 1);
    const int ty = tid >> 4;
    const int gy = ty0 + ty;
    const int gx = tx0 + tx;
    const size_t pix = (size_t)gy * HW + gx;
    float* ob = out + (size_t)b * CHN * PIX;

    // life gate: 3x3 max-pool of channel 3, NON-circular (-inf padding)
    float mx = -INFINITY;
    #pragma unroll
    for (int dy = -1; dy <= 1; dy++) {
        #pragma unroll
        for (int dx = -1; dx <= 1; dx++) {
            int Y = gy + dy, X = gx + dx;
            if (Y >= 0 && Y < HW && X >= 0 && X < HW)
                mx = fmaxf(mx, s_x[3][ty + 1 + dy][tx + 1 + dx]);
        }
    }
    float life = (mx > 0.1f) ? 1.0f : 0.0f;
    float mask = floorf(rnd[(size_t)b * PIX + pix] + 0.5f);
    bool active = (life * mask) != 0.0f;

    // gene channels always copied
    #pragma unroll
    for (int c = OUTC; c < CHN; c++)
        ob[(size_t)c * PIX + pix] = s_x[c][ty + 1][tx + 1];

    if (!active) {
        // y * gate == 0 exactly: output = x
        #pragma unroll
        for (int c = 0; c < OUTC; c++)
            ob[(size_t)c * PIX + pix] = s_x[c][ty + 1][tx + 1];
    } else {
        int idx = atomicAdd(&s_cnt, 1);
        s_list[idx] = (unsigned short)tid;
    }
    __syncthreads();

    // =========================== Phase B ===========================
    const int n = s_cnt;
    if (tid < n) {
        const int p  = s_list[tid];
        const int pty = p >> 4;
        const int ptx = p & 15;

        // recompute perception for the compacted pixel (cheap vs MLP)
        float pr[PERC];
        compute_perc(s_x, pty, ptx, pr);

        float o[12];
        #pragma unroll
        for (int i = 0; i < 12; i++) o[i] = 0.0f;

        const float4* w1_4  = reinterpret_cast<const float4*>(s_w1);
        const float4* w2t_4 = reinterpret_cast<const float4*>(s_w2t);

        #pragma unroll 4
        for (int h = 0; h < HIDDEN; h++) {
            float acc = s_b[h];
            #pragma unroll
            for (int q = 0; q < 9; q++) {
                float4 w = w1_4[h * 9 + q];       // broadcast LDS.128
                acc = fmaf(w.x, pr[4*q],   acc);
                acc = fmaf(w.y, pr[4*q+1], acc);
                acc = fmaf(w.z, pr[4*q+2], acc);
                acc = fmaf(w.w, pr[4*q+3], acc);
            }
            acc = fmaxf(acc, 0.0f) + 0.01f * fminf(acc, 0.0f);  // leaky relu
            #pragma unroll
            for (int q = 0; q < 3; q++) {
                float4 w = w2t_4[h * 3 + q];      // broadcast LDS.128
                o[4*q]   = fmaf(w.x, acc, o[4*q]);
                o[4*q+1] = fmaf(w.y, acc, o[4*q+1]);
                o[4*q+2] = fmaf(w.z, acc, o[4*q+2]);
                o[4*q+3] = fmaf(w.w, acc, o[4*q+3]);
            }
        }

        const int agy = ty0 + pty;
        const int agx = tx0 + ptx;
        const size_t apix = (size_t)agy * HW + agx;
        #pragma unroll
        for (int c = 0; c < OUTC; c++)
            ob[(size_t)c * PIX + apix] = s_x[c][pty + 1][ptx + 1] + o[c];
    }
}

extern "C" void kernel_launch(void* const* d_in, const int* in_sizes, int n_in,
                              void* d_out, int out_size) {
    const float* x   = (const float*)d_in[0];
    const float* rnd = (const float*)d_in[1];
    const float* w1w = (const float*)d_in[2];
    const float* w1b = (const float*)d_in[3];
    const float* w2w = (const float*)d_in[4];
    float* out = (float*)d_out;

    dim3 grid(HW / TILE, HW / TILE, 16);   // 4096 blocks
    isoca_fused_kernel<<<grid, 256>>>(x, rnd, w1w, w1b, w2w, out);
}

// round 4
// speedup vs baseline: 2.0223x; 1.3350x over previous
#include <cuda_runtime.h>
#include <math.h>

#define TILE   32
#define HALO   34   // TILE + 2
#define CHN    12
#define HIDDEN 128
#define PERC   36
#define OUTC   9    // CHN - GENE_SIZE
#define HW     256
#define PIX    (HW*HW)

// dynamic smem layout (floats)
#define OFF_X    0                         // 12*34*34 = 13872 floats
#define OFF_W1   (OFF_X + CHN*HALO*HALO)   // 128*36 = 4608
#define OFF_W2T  (OFF_W1 + HIDDEN*PERC)    // 128*12 = 1536
#define OFF_B    (OFF_W2T + HIDDEN*12)     // 128
#define OFF_LIST (OFF_B + HIDDEN)          // 1024 u16 = 512 floats
#define OFF_CNT  (OFF_LIST + 512)          // 1 int
#define SMEM_FLOATS (OFF_CNT + 1)
#define SMEM_BYTES  (SMEM_FLOATS * 4)      // ~83.5 KB

__device__ __forceinline__ void compute_perc(const float* __restrict__ sx,
                                             int ty, int tx, float* perc)
{
    #pragma unroll
    for (int c = 0; c < CHN; c++) {
        const float* r0 = sx + c * (HALO*HALO) + ty * HALO + tx;
        float n00 = r0[0],        n01 = r0[1],        n02 = r0[2];
        float n10 = r0[HALO],     n11 = r0[HALO+1],   n12 = r0[HALO+2];
        float n20 = r0[2*HALO],   n21 = r0[2*HALO+1], n22 = r0[2*HALO+2];
        float lap = (n00 + n02 + n20 + n22) + 2.0f * (n01 + n10 + n12 + n21) - 12.0f * n11;
        float gxv = (n02 - n00) + 2.0f * (n12 - n10) + (n22 - n20);
        float gyv = (n20 - n00) + 2.0f * (n21 - n01) + (n22 - n02);
        perc[2*c]     = n11;
        perc[2*c + 1] = lap;
        perc[24 + c]  = sqrtf(gxv * gxv + gyv * gyv + 1e-8f);
    }
}

__global__ void __launch_bounds__(256)
isoca_fused_kernel(const float* __restrict__ x,
                   const float* __restrict__ rnd,
                   const float* __restrict__ w1w,
                   const float* __restrict__ w1b,
                   const float* __restrict__ w2w,
                   float* __restrict__ out)
{
    extern __shared__ float sm[];
    float* s_x   = sm + OFF_X;
    float* s_w1  = sm + OFF_W1;
    float* s_w2t = sm + OFF_W2T;
    float* s_b   = sm + OFF_B;
    unsigned short* s_list = (unsigned short*)(sm + OFF_LIST);
    int* s_cnt = (int*)(sm + OFF_CNT);

    const int b   = blockIdx.z;
    const int ty0 = blockIdx.y * TILE;
    const int tx0 = blockIdx.x * TILE;
    const int tid = threadIdx.x;

    if (tid == 0) *s_cnt = 0;

    // ---- stage weights ----
    for (int i = tid; i < HIDDEN * PERC; i += 256) s_w1[i] = w1w[i];
    for (int i = tid; i < HIDDEN * 12; i += 256) {
        int h = i / 12, o = i % 12;
        s_w2t[i] = (o < OUTC) ? w2w[o * HIDDEN + h] : 0.0f;
    }
    if (tid < HIDDEN) s_b[tid] = w1b[tid];

    // ---- stage x tile (+1 halo, circular wrap) ----
    const float* xb = x + (size_t)b * CHN * PIX;
    for (int i = tid; i < CHN * HALO * HALO; i += 256) {
        int c  = i / (HALO * HALO);
        int r  = i % (HALO * HALO);
        int yy = r / HALO;
        int xx = r % HALO;
        int gyw = (ty0 + yy - 1) & (HW - 1);
        int gxw = (tx0 + xx - 1) & (HW - 1);
        s_x[c * (HALO*HALO) + yy * HALO + xx] = xb[(size_t)c * PIX + gyw * HW + gxw];
    }
    __syncthreads();

    // =========================== Phase A ===========================
    float* ob = out + (size_t)b * CHN * PIX;

    for (int p = tid; p < TILE * TILE; p += 256) {
        const int ty = p >> 5;
        const int tx = p & 31;
        const int gy = ty0 + ty;
        const int gx = tx0 + tx;
        const size_t pix = (size_t)gy * HW + gx;

        // life gate: 3x3 max-pool of channel 3, NON-circular (-inf edge)
        float mx = -INFINITY;
        #pragma unroll
        for (int dy = -1; dy <= 1; dy++) {
            #pragma unroll
            for (int dx = -1; dx <= 1; dx++) {
                int Y = gy + dy, X = gx + dx;
                if (Y >= 0 && Y < HW && X >= 0 && X < HW)
                    mx = fmaxf(mx, s_x[3*(HALO*HALO) + (ty+1+dy)*HALO + (tx+1+dx)]);
            }
        }
        float life = (mx > 0.1f) ? 1.0f : 0.0f;
        float mask = floorf(rnd[(size_t)b * PIX + pix] + 0.5f);
        bool active = (life * mask) != 0.0f;

        // gene channels always copied
        #pragma unroll
        for (int c = OUTC; c < CHN; c++)
            ob[(size_t)c * PIX + pix] = s_x[c*(HALO*HALO) + (ty+1)*HALO + (tx+1)];

        if (!active) {
            // y * gate == 0 exactly: output = x
            #pragma unroll
            for (int c = 0; c < OUTC; c++)
                ob[(size_t)c * PIX + pix] = s_x[c*(HALO*HALO) + (ty+1)*HALO + (tx+1)];
        } else {
            int idx = atomicAdd(s_cnt, 1);
            s_list[idx] = (unsigned short)p;
        }
    }
    __syncthreads();

    // =========================== Phase B: 2 pixels per thread ===========================
    const int n = *s_cnt;
    const float4* w1_4  = reinterpret_cast<const float4*>(s_w1);
    const float4* w2t_4 = reinterpret_cast<const float4*>(s_w2t);

    for (int base = 0; base < n; base += 512) {
        const int i1 = base + tid;
        const int i2 = base + 256 + tid;
        const bool v1 = i1 < n;
        const bool v2 = i2 < n;
        if (!v1) break;

        const int p1 = s_list[i1];
        const int p2 = v2 ? s_list[i2] : 0;
        const int ty1 = p1 >> 5, tx1 = p1 & 31;
        const int ty2 = p2 >> 5, tx2 = p2 & 31;

        float pr1[PERC], pr2[PERC];
        compute_perc(s_x, ty1, tx1, pr1);
        compute_perc(s_x, ty2, tx2, pr2);   // garbage-safe if !v2 (valid floats, no store)

        float o1[12], o2[12];
        #pragma unroll
        for (int i = 0; i < 12; i++) { o1[i] = 0.0f; o2[i] = 0.0f; }

        #pragma unroll 2
        for (int h = 0; h < HIDDEN; h++) {
            float a1 = s_b[h];
            float a2 = a1;
            #pragma unroll
            for (int q = 0; q < 9; q++) {
                float4 w = w1_4[h * 9 + q];           // one LDS.128, two pixels
                a1 = fmaf(w.x, pr1[4*q],   a1);  a2 = fmaf(w.x, pr2[4*q],   a2);
                a1 = fmaf(w.y, pr1[4*q+1], a1);  a2 = fmaf(w.y, pr2[4*q+1], a2);
                a1 = fmaf(w.z, pr1[4*q+2], a1);  a2 = fmaf(w.z, pr2[4*q+2], a2);
                a1 = fmaf(w.w, pr1[4*q+3], a1);  a2 = fmaf(w.w, pr2[4*q+3], a2);
            }
            a1 = fmaxf(a1, 0.0f) + 0.01f * fminf(a1, 0.0f);
            a2 = fmaxf(a2, 0.0f) + 0.01f * fminf(a2, 0.0f);
            #pragma unroll
            for (int q = 0; q < 3; q++) {
                float4 w = w2t_4[h * 3 + q];          // one LDS.128, two pixels
                o1[4*q]   = fmaf(w.x, a1, o1[4*q]);   o2[4*q]   = fmaf(w.x, a2, o2[4*q]);
                o1[4*q+1] = fmaf(w.y, a1, o1[4*q+1]); o2[4*q+1] = fmaf(w.y, a2, o2[4*q+1]);
                o1[4*q+2] = fmaf(w.z, a1, o1[4*q+2]); o2[4*q+2] = fmaf(w.z, a2, o2[4*q+2]);
                o1[4*q+3] = fmaf(w.w, a1, o1[4*q+3]); o2[4*q+3] = fmaf(w.w, a2, o2[4*q+3]);
            }
        }

        {
            const size_t apix = (size_t)(ty0 + ty1) * HW + (tx0 + tx1);
            #pragma unroll
            for (int c = 0; c < OUTC; c++)
                ob[(size_t)c * PIX + apix] =
                    s_x[c*(HALO*HALO) + (ty1+1)*HALO + (tx1+1)] + o1[c];
        }
        if (v2) {
            const size_t apix = (size_t)(ty0 + ty2) * HW + (tx0 + tx2);
            #pragma unroll
            for (int c = 0; c < OUTC; c++)
                ob[(size_t)c * PIX + apix] =
                    s_x[c*(HALO*HALO) + (ty2+1)*HALO + (tx2+1)] + o2[c];
        }
    }
}

extern "C" void kernel_launch(void* const* d_in, const int* in_sizes, int n_in,
                              void* d_out, int out_size) {
    const float* x   = (const float*)d_in[0];
    const float* rnd = (const float*)d_in[1];
    const float* w1w = (const float*)d_in[2];
    const float* w1b = (const float*)d_in[3];
    const float* w2w = (const float*)d_in[4];
    float* out = (float*)d_out;

    cudaFuncSetAttribute(isoca_fused_kernel,
                         cudaFuncAttributeMaxDynamicSharedMemorySize, SMEM_BYTES);

    dim3 grid(HW / TILE, HW / TILE, 16);   // (8, 8, 16) = 1024 blocks
    isoca_fused_kernel<<<grid, 256, SMEM_BYTES>>>(x, rnd, w1w, w1b, w2w, out);
}

// round 5
// speedup vs baseline: 2.1350x; 1.0558x over previous
#include <cuda_runtime.h>
#include <math.h>

#define TILE   32
#define HALO   34   // TILE + 2
#define CHN    12
#define HIDDEN 128
#define PERC   36
#define OUTC   9    // CHN - GENE_SIZE
#define HW     256
#define PIX    (HW*HW)

// dynamic smem layout (floats)
#define OFF_X    0                         // 12*34*34 = 13872 floats
#define OFF_W1   (OFF_X + CHN*HALO*HALO)   // 128*36 = 4608   (byte off 55488, 16B aligned)
#define OFF_W2T  (OFF_W1 + HIDDEN*PERC)    // 128*12 = 1536   (byte off 73920, 16B aligned)
#define OFF_B    (OFF_W2T + HIDDEN*12)     // 128
#define OFF_LIST (OFF_B + HIDDEN)          // 1024 u16 = 512 floats
#define OFF_CNT  (OFF_LIST + 512)          // 1 int
#define SMEM_FLOATS (OFF_CNT + 1)
#define SMEM_BYTES  (SMEM_FLOATS * 4)      // ~83.5 KB

typedef unsigned long long u64;

__device__ __forceinline__ u64 pack2(float lo, float hi) {
    u64 r; asm("mov.b64 %0, {%1, %2};" : "=l"(r) : "f"(lo), "f"(hi)); return r;
}
__device__ __forceinline__ void unpack2(u64 v, float& lo, float& hi) {
    asm("mov.b64 {%0, %1}, %2;" : "=f"(lo), "=f"(hi) : "l"(v));
}
// packed dual FP32 FMA: d = a*b + c elementwise on (lo,hi)
__device__ __forceinline__ u64 ffma2(u64 a, u64 b, u64 c) {
    u64 d; asm("fma.rn.f32x2 %0, %1, %2, %3;" : "=l"(d) : "l"(a), "l"(b), "l"(c)); return d;
}

__device__ __forceinline__ void compute_perc(const float* __restrict__ sx,
                                             int ty, int tx, float* perc)
{
    #pragma unroll
    for (int c = 0; c < CHN; c++) {
        const float* r0 = sx + c * (HALO*HALO) + ty * HALO + tx;
        float n00 = r0[0],        n01 = r0[1],        n02 = r0[2];
        float n10 = r0[HALO],     n11 = r0[HALO+1],   n12 = r0[HALO+2];
        float n20 = r0[2*HALO],   n21 = r0[2*HALO+1], n22 = r0[2*HALO+2];
        float lap = (n00 + n02 + n20 + n22) + 2.0f * (n01 + n10 + n12 + n21) - 12.0f * n11;
        float gxv = (n02 - n00) + 2.0f * (n12 - n10) + (n22 - n20);
        float gyv = (n20 - n00) + 2.0f * (n21 - n01) + (n22 - n02);
        perc[2*c]     = n11;
        perc[2*c + 1] = lap;
        perc[24 + c]  = sqrtf(gxv * gxv + gyv * gyv + 1e-8f);
    }
}

__global__ void __launch_bounds__(256)
isoca_fused_kernel(const float* __restrict__ x,
                   const float* __restrict__ rnd,
                   const float* __restrict__ w1w,
                   const float* __restrict__ w1b,
                   const float* __restrict__ w2w,
                   float* __restrict__ out)
{
    extern __shared__ float sm[];
    float* s_x   = sm + OFF_X;
    float* s_w1  = sm + OFF_W1;
    float* s_w2t = sm + OFF_W2T;
    float* s_b   = sm + OFF_B;
    unsigned short* s_list = (unsigned short*)(sm + OFF_LIST);
    int* s_cnt = (int*)(sm + OFF_CNT);

    const int b   = blockIdx.z;
    const int ty0 = blockIdx.y * TILE;
    const int tx0 = blockIdx.x * TILE;
    const int tid = threadIdx.x;

    if (tid == 0) *s_cnt = 0;

    // ---- stage weights ----
    for (int i = tid; i < HIDDEN * PERC; i += 256) s_w1[i] = w1w[i];
    for (int i = tid; i < HIDDEN * 12; i += 256) {
        int h = i / 12, o = i % 12;
        s_w2t[i] = (o < OUTC) ? w2w[o * HIDDEN + h] : 0.0f;
    }
    if (tid < HIDDEN) s_b[tid] = w1b[tid];

    // ---- stage x tile (+1 halo, circular wrap) ----
    const float* xb = x + (size_t)b * CHN * PIX;
    for (int i = tid; i < CHN * HALO * HALO; i += 256) {
        int c  = i / (HALO * HALO);
        int r  = i % (HALO * HALO);
        int yy = r / HALO;
        int xx = r % HALO;
        int gyw = (ty0 + yy - 1) & (HW - 1);
        int gxw = (tx0 + xx - 1) & (HW - 1);
        s_x[c * (HALO*HALO) + yy * HALO + xx] = xb[(size_t)c * PIX + gyw * HW + gxw];
    }
    __syncthreads();

    // =========================== Phase A ===========================
    float* ob = out + (size_t)b * CHN * PIX;

    for (int p = tid; p < TILE * TILE; p += 256) {
        const int ty = p >> 5;
        const int tx = p & 31;
        const int gy = ty0 + ty;
        const int gx = tx0 + tx;
        const size_t pix = (size_t)gy * HW + gx;

        // life gate: 3x3 max-pool of channel 3, NON-circular (-inf edge)
        float mx = -INFINITY;
        #pragma unroll
        for (int dy = -1; dy <= 1; dy++) {
            #pragma unroll
            for (int dx = -1; dx <= 1; dx++) {
                int Y = gy + dy, X = gx + dx;
                if (Y >= 0 && Y < HW && X >= 0 && X < HW)
                    mx = fmaxf(mx, s_x[3*(HALO*HALO) + (ty+1+dy)*HALO + (tx+1+dx)]);
            }
        }
        float life = (mx > 0.1f) ? 1.0f : 0.0f;
        float mask = floorf(rnd[(size_t)b * PIX + pix] + 0.5f);
        bool active = (life * mask) != 0.0f;

        // gene channels always copied
        #pragma unroll
        for (int c = OUTC; c < CHN; c++)
            ob[(size_t)c * PIX + pix] = s_x[c*(HALO*HALO) + (ty+1)*HALO + (tx+1)];

        if (!active) {
            // y * gate == 0 exactly: output = x
            #pragma unroll
            for (int c = 0; c < OUTC; c++)
                ob[(size_t)c * PIX + pix] = s_x[c*(HALO*HALO) + (ty+1)*HALO + (tx+1)];
        } else {
            int idx = atomicAdd(s_cnt, 1);
            s_list[idx] = (unsigned short)p;
        }
    }
    __syncthreads();

    // ============== Phase B: 2 pixels/thread, packed f32x2 MLP ==============
    const int n = *s_cnt;

    for (int base = 0; base < n; base += 512) {
        const int i1 = base + tid;
        const int i2 = base + 256 + tid;
        const bool v1 = i1 < n;
        const bool v2 = i2 < n;
        if (!v1) break;

        const int p1 = s_list[i1];
        const int p2 = v2 ? s_list[i2] : 0;
        const int ty1 = p1 >> 5, tx1 = p1 & 31;
        const int ty2 = p2 >> 5, tx2 = p2 & 31;

        float pr1[PERC], pr2[PERC];
        compute_perc(s_x, ty1, tx1, pr1);
        compute_perc(s_x, ty2, tx2, pr2);   // garbage-safe if !v2 (valid floats, no store)

        // pre-pack perc into (k, k+1) pairs — reused across all 128 h
        u64 p1p[18], p2p[18];
        #pragma unroll
        for (int k = 0; k < 18; k++) {
            p1p[k] = pack2(pr1[2*k], pr1[2*k+1]);
            p2p[k] = pack2(pr2[2*k], pr2[2*k+1]);
        }

        // output accumulators: 6 (o,o+1) pairs per pixel (12 padded outs)
        u64 o1p[6], o2p[6];
        #pragma unroll
        for (int i = 0; i < 6; i++) { o1p[i] = 0ull; o2p[i] = 0ull; }

        #pragma unroll 2
        for (int h = 0; h < HIDDEN; h++) {
            const ulonglong2* wr = reinterpret_cast<const ulonglong2*>(s_w1 + h * PERC);
            float bh = s_b[h];
            u64 acc1 = pack2(bh, 0.0f);
            u64 acc2 = acc1;
            #pragma unroll
            for (int q = 0; q < 9; q++) {
                ulonglong2 w = wr[q];            // LDS.128: two natural (k,k+1) weight pairs
                acc1 = ffma2(w.x, p1p[2*q],   acc1);
                acc2 = ffma2(w.x, p2p[2*q],   acc2);
                acc1 = ffma2(w.y, p1p[2*q+1], acc1);
                acc2 = ffma2(w.y, p2p[2*q+1], acc2);
            }
            float e1, f1, e2, f2;
            unpack2(acc1, e1, f1);
            unpack2(acc2, e2, f2);
            float a1 = e1 + f1;
            float a2 = e2 + f2;
            a1 = fmaxf(a1, 0.0f) + 0.01f * fminf(a1, 0.0f);  // leaky relu
            a2 = fmaxf(a2, 0.0f) + 0.01f * fminf(a2, 0.0f);
            u64 a1p = pack2(a1, a1);
            u64 a2p = pack2(a2, a2);

            const ulonglong2* w2r = reinterpret_cast<const ulonglong2*>(s_w2t + h * 12);
            #pragma unroll
            for (int q = 0; q < 3; q++) {
                ulonglong2 w = w2r[q];           // LDS.128: two natural (o,o+1) pairs
                o1p[2*q]   = ffma2(w.x, a1p, o1p[2*q]);
                o2p[2*q]   = ffma2(w.x, a2p, o2p[2*q]);
                o1p[2*q+1] = ffma2(w.y, a1p, o1p[2*q+1]);
                o2p[2*q+1] = ffma2(w.y, a2p, o2p[2*q+1]);
            }
        }

        // unpack outputs and store
        float o1[12], o2[12];
        #pragma unroll
        for (int q = 0; q < 6; q++) {
            unpack2(o1p[q], o1[2*q], o1[2*q+1]);
            unpack2(o2p[q], o2[2*q], o2[2*q+1]);
        }

        {
            const size_t apix = (size_t)(ty0 + ty1) * HW + (tx0 + tx1);
            #pragma unroll
            for (int c = 0; c < OUTC; c++)
                ob[(size_t)c * PIX + apix] =
                    s_x[c*(HALO*HALO) + (ty1+1)*HALO + (tx1+1)] + o1[c];
        }
        if (v2) {
            const size_t apix = (size_t)(ty0 + ty2) * HW + (tx0 + tx2);
            #pragma unroll
            for (int c = 0; c < OUTC; c++)
                ob[(size_t)c * PIX + apix] =
                    s_x[c*(HALO*HALO) + (ty2+1)*HALO + (tx2+1)] + o2[c];
        }
    }
}

extern "C" void kernel_launch(void* const* d_in, const int* in_sizes, int n_in,
                              void* d_out, int out_size) {
    const float* x   = (const float*)d_in[0];
    const float* rnd = (const float*)d_in[1];
    const float* w1w = (const float*)d_in[2];
    const float* w1b = (const float*)d_in[3];
    const float* w2w = (const float*)d_in[4];
    float* out = (float*)d_out;

    cudaFuncSetAttribute(isoca_fused_kernel,
                         cudaFuncAttributeMaxDynamicSharedMemorySize, SMEM_BYTES);

    dim3 grid(HW / TILE, HW / TILE, 16);   // (8, 8, 16) = 1024 blocks
    isoca_fused_kernel<<<grid, 256, SMEM_BYTES>>>(x, rnd, w1w, w1b, w2w, out);
}